// round 1
// baseline (speedup 1.0000x reference)
#include <cuda_runtime.h>
#include <math.h>

#define BB   8
#define NN   2048
#define KNB  32
#define FIN  256
#define FOUT 256
#define CC   512          // 2*FOUT
#define ROWS 16384        // BB*NN

#define TM 64             // rows per block in GEMM
#define KF 64             // f-chunk for W tile

// ---------------- scratch (device globals; no allocation allowed) -------------
__device__ float g_xT[(size_t)BB * FIN * NN];   // [b][f][n]  16 MB
__device__ float g_WxT[FIN * FOUT];             // [f][o]
__device__ float g_WnT[FIN * FOUT];             // [f][o]
__device__ float g_partials[256 * 1024];        // per-block [sum(512); sumsq(512)]
__device__ float g_scale[CC];
__device__ float g_shift[CC];

// ---------------- f32x2 helpers ----------------------------------------------
__device__ __forceinline__ unsigned long long pk2(float lo, float hi) {
    unsigned long long r;
    asm("mov.b64 %0, {%1, %2};" : "=l"(r) : "f"(lo), "f"(hi));
    return r;
}
__device__ __forceinline__ void fma2(unsigned long long& d,
                                     unsigned long long a,
                                     unsigned long long b) {
    asm("fma.rn.f32x2 %0, %1, %2, %0;" : "+l"(d) : "l"(a), "l"(b));
}
__device__ __forceinline__ float2 up2(unsigned long long v) {
    float lo, hi;
    asm("mov.b64 {%0, %1}, %2;" : "=f"(lo), "=f"(hi) : "l"(v));
    return make_float2(lo, hi);
}

// ---------------- k0: tiled transpose  out[C][R] = in[R][C] -------------------
__global__ void ktrans(const float* __restrict__ in, float* __restrict__ out,
                       int R, int C, long long inStride, long long outStride) {
    __shared__ float tile[32][33];
    const float* src = in + (long long)blockIdx.z * inStride;
    float* dst = out + (long long)blockIdx.z * outStride;
    int rb = blockIdx.y * 32, cb = blockIdx.x * 32;
    int tx = threadIdx.x, ty = threadIdx.y;
#pragma unroll
    for (int j = 0; j < 32; j += 8)
        tile[ty + j][tx] = src[(long long)(rb + ty + j) * C + cb + tx];
    __syncthreads();
#pragma unroll
    for (int j = 0; j < 32; j += 8)
        dst[(long long)(cb + ty + j) * R + rb + tx] = tile[tx][ty + j];
}

// ---------------- k1: fused gather-mean + dual GEMM ---------------------------
// grid (NN/TM, BB), 512 threads, dynamic smem 192KB
__global__ __launch_bounds__(512, 1)
void k1_gemm(const float* __restrict__ x,
             const int* __restrict__ idx,
             const float* __restrict__ WxT, const float* __restrict__ Wxb,
             const float* __restrict__ WnT, const float* __restrict__ Wnb,
             const float* __restrict__ xT,
             float* __restrict__ out) {
    extern __shared__ float sm[];
    float* xs_t = sm;           // [256 f][64 r]
    float* xm_t = sm + 16384;   // [256 f][64 r]
    float* wt   = sm + 32768;   // [64 f][256 o]
    int*   sIdx = (int*)(sm + 32768);   // aliased: used only before wt

    const int tid = threadIdx.x;
    const int b   = blockIdx.y;
    const int n0  = blockIdx.x * TM;

    // ---- load idx tile (64 rows x 32) ----
    {
        const int* src = idx + n0 * KNB;
        for (int i = tid; i < TM * KNB; i += 512) sIdx[i] = src[i];
    }
    // ---- load xs_t from pre-transposed xT (conflict-free STS.128) ----
    {
        const float* src = xT + (size_t)b * FIN * NN + n0;
        for (int i = tid; i < FIN * (TM / 4); i += 512) {
            int f = i >> 4, rq = i & 15;
            float4 v = *(const float4*)(src + (size_t)f * NN + rq * 4);
            *(float4*)(xs_t + f * TM + rq * 4) = v;
        }
    }
    __syncthreads();

    // ---- gather-mean: 8 threads per row, each covers 32 consecutive f ----
    {
        const int r  = tid >> 3;
        const int l8 = tid & 7;
        const float* xb = x + (size_t)b * NN * FIN + l8 * 32;
        float4 acc[8];
#pragma unroll
        for (int j = 0; j < 8; j++) acc[j] = make_float4(0.f, 0.f, 0.f, 0.f);
#pragma unroll 2
        for (int k = 0; k < KNB; k++) {
            const float4* s4 = (const float4*)(xb + (size_t)sIdx[r * KNB + k] * FIN);
#pragma unroll
            for (int j = 0; j < 8; j++) {
                float4 v = s4[j];
                acc[j].x += v.x; acc[j].y += v.y; acc[j].z += v.z; acc[j].w += v.w;
            }
        }
        const float inv = 1.0f / 32.0f;
#pragma unroll
        for (int j = 0; j < 8; j++) {
            int f = l8 * 32 + j * 4;
            xm_t[(f + 0) * TM + r] = acc[j].x * inv;
            xm_t[(f + 1) * TM + r] = acc[j].y * inv;
            xm_t[(f + 2) * TM + r] = acc[j].z * inv;
            xm_t[(f + 3) * TM + r] = acc[j].w * inv;
        }
    }
    __syncthreads();   // sIdx dead; wt may now overwrite

    const int rg = tid >> 6;          // 0..7  (8 rows each)
    const int cg = tid & 63;          // 0..63 (4 cols each)
    const int r0 = rg * 8;
    const int c0 = cg * 4;

#pragma unroll 1
    for (int pass = 0; pass < 2; pass++) {
        const float* A  = pass ? xm_t : xs_t;
        const float* WT = pass ? WnT : WxT;
        const float* Wb = pass ? Wnb : Wxb;

        unsigned long long acc[16];   // [rowpair 0..3][col 0..3]
#pragma unroll
        for (int i = 0; i < 16; i++) acc[i] = 0ull;

        for (int kc = 0; kc < FIN; kc += KF) {
            __syncthreads();
            // load W chunk [KF][256] from pre-transposed WT (conflict-free)
            for (int i = tid; i < KF * (FOUT / 4); i += 512) {
                int f = i >> 6, oq = i & 63;
                float4 v = *(const float4*)(WT + (size_t)(kc + f) * FOUT + oq * 4);
                *(float4*)(wt + f * FOUT + oq * 4) = v;
            }
            __syncthreads();
#pragma unroll 4
            for (int f = 0; f < KF; f++) {
                const float* Af = A + (kc + f) * TM + r0;
                // a: 8 rows as 4 f32x2 row-pairs (two broadcast LDS.128)
                ulonglong2 au0 = *(const ulonglong2*)(Af);
                ulonglong2 au1 = *(const ulonglong2*)(Af + 4);
                float4 bv = *(const float4*)(wt + f * FOUT + c0);
                unsigned long long b0 = pk2(bv.x, bv.x);
                unsigned long long b1 = pk2(bv.y, bv.y);
                unsigned long long b2 = pk2(bv.z, bv.z);
                unsigned long long b3 = pk2(bv.w, bv.w);
                fma2(acc[0],  au0.x, b0); fma2(acc[1],  au0.x, b1);
                fma2(acc[2],  au0.x, b2); fma2(acc[3],  au0.x, b3);
                fma2(acc[4],  au0.y, b0); fma2(acc[5],  au0.y, b1);
                fma2(acc[6],  au0.y, b2); fma2(acc[7],  au0.y, b3);
                fma2(acc[8],  au1.x, b0); fma2(acc[9],  au1.x, b1);
                fma2(acc[10], au1.x, b2); fma2(acc[11], au1.x, b3);
                fma2(acc[12], au1.y, b0); fma2(acc[13], au1.y, b1);
                fma2(acc[14], au1.y, b2); fma2(acc[15], au1.y, b3);
            }
        }

        // epilogue: +bias, write raw h to out
        float4 bias = *(const float4*)(Wb + c0);
        float* obase = out + ((size_t)b * NN + n0 + r0) * CC + pass * FOUT + c0;
#pragma unroll
        for (int i = 0; i < 4; i++) {
            float2 p0 = up2(acc[i * 4 + 0]);
            float2 p1 = up2(acc[i * 4 + 1]);
            float2 p2 = up2(acc[i * 4 + 2]);
            float2 p3 = up2(acc[i * 4 + 3]);
            float4 lo = make_float4(p0.x + bias.x, p1.x + bias.y,
                                    p2.x + bias.z, p3.x + bias.w);
            float4 hi = make_float4(p0.y + bias.x, p1.y + bias.y,
                                    p2.y + bias.z, p3.y + bias.w);
            *(float4*)(obase + (size_t)(2 * i) * CC)     = lo;
            *(float4*)(obase + (size_t)(2 * i + 1) * CC) = hi;
        }
    }
}

// ---------------- k2: row L2-normalize + relu (in place) + channel partials ---
// grid 256 blocks (64 rows each), 256 threads (8 warps x 8 rows)
__global__ __launch_bounds__(256)
void k2_norm(float* __restrict__ h, float* __restrict__ partials) {
    __shared__ float sp[8 * 1024];
    const int tid  = threadIdx.x;
    const int w    = tid >> 5;
    const int lane = tid & 31;
    float s1[16], s2[16];
#pragma unroll
    for (int i = 0; i < 16; i++) { s1[i] = 0.f; s2[i] = 0.f; }

    const int row0 = blockIdx.x * 64 + w * 8;
    for (int rr = 0; rr < 8; rr++) {
        float* hr = h + (size_t)(row0 + rr) * CC;
        float4 v[4];
        float ss = 0.f;
#pragma unroll
        for (int c = 0; c < 4; c++) {
            v[c] = *(const float4*)(hr + c * 128 + lane * 4);
            ss += v[c].x * v[c].x + v[c].y * v[c].y
                + v[c].z * v[c].z + v[c].w * v[c].w;
        }
#pragma unroll
        for (int o = 16; o; o >>= 1) ss += __shfl_xor_sync(0xffffffffu, ss, o);
        float inv = 1.0f / fmaxf(sqrtf(ss), 1e-12f);
#pragma unroll
        for (int c = 0; c < 4; c++) {
            float4 t;
            t.x = fmaxf(v[c].x * inv, 0.f);
            t.y = fmaxf(v[c].y * inv, 0.f);
            t.z = fmaxf(v[c].z * inv, 0.f);
            t.w = fmaxf(v[c].w * inv, 0.f);
            *(float4*)(hr + c * 128 + lane * 4) = t;
            s1[c * 4 + 0] += t.x; s2[c * 4 + 0] += t.x * t.x;
            s1[c * 4 + 1] += t.y; s2[c * 4 + 1] += t.y * t.y;
            s1[c * 4 + 2] += t.z; s2[c * 4 + 2] += t.z * t.z;
            s1[c * 4 + 3] += t.w; s2[c * 4 + 3] += t.w * t.w;
        }
    }
#pragma unroll
    for (int c = 0; c < 4; c++) {
#pragma unroll
        for (int j = 0; j < 4; j++) {
            int ch = c * 128 + lane * 4 + j;
            sp[w * 1024 + ch]       = s1[c * 4 + j];
            sp[w * 1024 + 512 + ch] = s2[c * 4 + j];
        }
    }
    __syncthreads();
    for (int i = tid; i < 1024; i += 256) {
        float s = 0.f;
#pragma unroll
        for (int w2 = 0; w2 < 8; w2++) s += sp[w2 * 1024 + i];
        partials[(size_t)blockIdx.x * 1024 + i] = s;
    }
}

// ---------------- k3: reduce partials -> per-channel scale/shift --------------
// grid 16, block 256: 32 channels per block, 8 threads per channel
__global__ void k3_stats(const float* __restrict__ partials,
                         const float* __restrict__ gamma,
                         const float* __restrict__ beta) {
    int ch   = blockIdx.x * 32 + (threadIdx.x >> 3);
    int part = threadIdx.x & 7;
    float s1 = 0.f, s2 = 0.f;
    for (int p = part; p < 256; p += 8) {
        s1 += partials[(size_t)p * 1024 + ch];
        s2 += partials[(size_t)p * 1024 + 512 + ch];
    }
#pragma unroll
    for (int o = 4; o; o >>= 1) {
        s1 += __shfl_xor_sync(0xffffffffu, s1, o);
        s2 += __shfl_xor_sync(0xffffffffu, s2, o);
    }
    if (part == 0) {
        const float invN = 1.0f / 16384.0f;
        float mu  = s1 * invN;
        float var = s2 * invN - mu * mu;
        float sc  = rsqrtf(var + 1e-5f) * gamma[ch];
        g_scale[ch] = sc;
        g_shift[ch] = beta[ch] - mu * sc;
    }
}

// ---------------- k4: apply BN elementwise (in place) -------------------------
__global__ __launch_bounds__(256)
void k4_bn(float* __restrict__ h) {
    int i  = blockIdx.x * 256 + threadIdx.x;     // float4 index
    int c0 = (i & 127) * 4;
    float4 v  = *((float4*)h + i);
    float4 sc = *(const float4*)(g_scale + c0);
    float4 sh = *(const float4*)(g_shift + c0);
    v.x = fmaf(v.x, sc.x, sh.x);
    v.y = fmaf(v.y, sc.y, sh.y);
    v.z = fmaf(v.z, sc.z, sh.z);
    v.w = fmaf(v.w, sc.w, sh.w);
    *((float4*)h + i) = v;
}

// ---------------- launch ------------------------------------------------------
extern "C" void kernel_launch(void* const* d_in, const int* in_sizes, int n_in,
                              void* d_out, int out_size) {
    const float* x     = (const float*)d_in[0];
    const int*   idx   = (const int*)d_in[1];
    const float* Wx_w  = (const float*)d_in[2];
    const float* Wx_b  = (const float*)d_in[3];
    const float* Wn_w  = (const float*)d_in[4];
    const float* Wn_b  = (const float*)d_in[5];
    const float* gamma = (const float*)d_in[6];
    const float* beta  = (const float*)d_in[7];
    float* out = (float*)d_out;

    float *xT, *WxT, *WnT, *parts;
    cudaGetSymbolAddress((void**)&xT,    g_xT);
    cudaGetSymbolAddress((void**)&WxT,   g_WxT);
    cudaGetSymbolAddress((void**)&WnT,   g_WnT);
    cudaGetSymbolAddress((void**)&parts, g_partials);

    dim3 tb(32, 8);
    // weight transposes: [o][f] -> [f][o]
    ktrans<<<dim3(8, 8, 1), tb>>>(Wx_w, WxT, 256, 256, 0, 0);
    ktrans<<<dim3(8, 8, 1), tb>>>(Wn_w, WnT, 256, 256, 0, 0);
    // x transpose per batch: [n][f] -> [f][n]
    ktrans<<<dim3(8, 64, BB), tb>>>(x, xT, NN, FIN,
                                    (long long)NN * FIN, (long long)FIN * NN);

    cudaFuncSetAttribute(k1_gemm, cudaFuncAttributeMaxDynamicSharedMemorySize,
                         196608);
    k1_gemm<<<dim3(NN / TM, BB), 512, 196608>>>(x, idx, WxT, Wx_b, WnT, Wn_b,
                                                xT, out);
    k2_norm<<<256, 256>>>(out, parts);
    k3_stats<<<16, 256>>>(parts, gamma, beta);
    k4_bn<<<ROWS * CC / 4 / 256, 256>>>(out);
}